// round 5
// baseline (speedup 1.0000x reference)
#include <cuda_runtime.h>
#include <cuda_bf16.h>
#include <math_constants.h>

// Problem constants
#define BATCH   2
#define NPTS    8192
#define KNN     11        // k+1 including self
#define LEN_IN  66        // 3*11 + 3*10 + 3
#define TPB     128
#define NGROUP  2         // split-K over candidates
#define QPB     (TPB / NGROUP)        // 64 queries per block
#define GRANGE  (NPTS / NGROUP)       // 4096 candidates per group
#define CHUNK   1024                  // candidates per group per smem iteration
#define NITER   (GRANGE / CHUNK)      // 4

// Collapsed weights (device scratch; no allocations allowed)
__device__ float g_W12[LEN_IN * 16];
__device__ float g_Wc [LEN_IN * 6];
__device__ float g_bc [6];

// ---------------------------------------------------------------------------
// Prologue: collapse W1@W2@W3 and the bias chain (tiny, one block).
// The reference MLP has no activation functions, so the whole head is affine:
//   pred = feats @ (W1@W2@W3) + ((b1@W2 + b2)@W3 + b3)
// ---------------------------------------------------------------------------
__global__ void combine_weights_kernel(const float* __restrict__ W1,
                                       const float* __restrict__ b1,
                                       const float* __restrict__ W2,
                                       const float* __restrict__ b2,
                                       const float* __restrict__ W3,
                                       const float* __restrict__ b3)
{
    int t = threadIdx.x;
    // W12 = W1[66,32] @ W2[32,16]
    for (int e = t; e < LEN_IN * 16; e += blockDim.x) {
        int r = e / 16, c = e % 16;
        float s = 0.f;
        for (int k = 0; k < 32; ++k) s += W1[r * 32 + k] * W2[k * 16 + c];
        g_W12[e] = s;
    }
    __syncthreads();
    // Wc = W12[66,16] @ W3[16,6]
    for (int e = t; e < LEN_IN * 6; e += blockDim.x) {
        int r = e / 6, c = e % 6;
        float s = 0.f;
        for (int k = 0; k < 16; ++k) s += g_W12[r * 16 + k] * W3[k * 6 + c];
        g_Wc[e] = s;
    }
    // bc = ((b1@W2)+b2)@W3 + b3
    if (t < 6) {
        float s = b3[t];
        for (int k = 0; k < 16; ++k) {
            float tb = b2[k];
            for (int m = 0; m < 32; ++m) tb += b1[m] * W2[m * 16 + k];
            s += tb * W3[k * 6 + t];
        }
        g_bc[t] = s;
    }
}

// ---------------------------------------------------------------------------
// Main fused kernel: split-K brute-force kNN (top-11 by d2) + exact merge +
// gather + collapsed linear head.
//   Block = 64 queries x 2 candidate groups (128 threads).
//   Warps 0-1: group 0 scans candidates [0, 4096)
//   Warps 2-3: group 1 scans candidates [4096, 8192)
//   All lanes of a warp read the same s_tile entry -> broadcast LDS.
// ---------------------------------------------------------------------------
__global__ void __launch_bounds__(TPB)
knn_mlp_kernel(const float* __restrict__ pos,
               const float* __restrict__ vel,
               const float* __restrict__ initc,
               float* __restrict__ out)
{
    __shared__ float4 s_tile[NGROUP * CHUNK];      // per-group candidate chunks
    __shared__ float  s_md[TPB * KNN];             // partial top-11 distances
    __shared__ int    s_mi[TPB * KNN];             // partial top-11 indices
    __shared__ float  s_Wc[LEN_IN * 6];
    __shared__ float  s_bc[6];

    const int tid  = threadIdx.x;
    const int grp  = tid >> 6;                     // 0 or 1
    const int qloc = tid & (QPB - 1);              // query within block
    const int q    = blockIdx.x * QPB + qloc;      // global query id
    const int bb   = q >> 13;                      // q / 8192 (batch)
    const int i    = q & (NPTS - 1);

    const float* __restrict__ bpos = pos + (size_t)bb * NPTS * 3;
    const float* __restrict__ bvel = vel + (size_t)bb * NPTS * 3;

    for (int t = tid; t < LEN_IN * 6; t += TPB) s_Wc[t] = g_Wc[t];
    if (tid < 6) s_bc[tid] = g_bc[tid];

    // Query point; sq computed with the SAME op sequence as the tile loader so
    // the self-distance is exactly 0.
    const float qx = bpos[i * 3 + 0];
    const float qy = bpos[i * 3 + 1];
    const float qz = bpos[i * 3 + 2];
    float qs = qx * qx; qs = fmaf(qy, qy, qs); qs = fmaf(qz, qz, qs);

    // Per-group sorted top-11 (ascending), register-resident.
    float bd[KNN];
    int   bi[KNN];
#pragma unroll
    for (int k = 0; k < KNN; ++k) { bd[k] = CUDART_INF_F; bi[k] = 0; }

    const float4* __restrict__ mytile = s_tile + (grp << 10);

    for (int it = 0; it < NITER; ++it) {
        __syncthreads();
        // Cooperative load of both groups' chunks: (x,y,z,sq)
        for (int t = tid; t < NGROUP * CHUNK; t += TPB) {
            const int g  = t >> 10;                       // which group's chunk
            const int r  = t & (CHUNK - 1);
            const int j  = g * GRANGE + it * CHUNK + r;   // global candidate id
            const float x = bpos[j * 3 + 0];
            const float y = bpos[j * 3 + 1];
            const float z = bpos[j * 3 + 2];
            float s = x * x; s = fmaf(y, y, s); s = fmaf(z, z, s);
            s_tile[t] = make_float4(x, y, z, s);
        }
        __syncthreads();

        const int idxbase = grp * GRANGE + it * CHUNK;
#pragma unroll 8
        for (int t = 0; t < CHUNK; ++t) {
            const float4 p = mytile[t];
            float d = qx * p.x; d = fmaf(qy, p.y, d); d = fmaf(qz, p.z, d);
            const float d2 = fmaf(-2.0f, d, qs + p.w);
            if (d2 < bd[KNN - 1]) {
                // Sorted insert; strict '<' + ascending scan keeps lower index
                // first on ties (matches jax.lax.top_k).
                float dv = d2; int id = idxbase + t;
#pragma unroll
                for (int k = 0; k < KNN; ++k) {
                    if (dv < bd[k]) {
                        float td = bd[k]; bd[k] = dv; dv = td;
                        int   ti = bi[k]; bi[k] = id; id = ti;
                    }
                }
            }
        }
    }

    // Publish partial lists.
#pragma unroll
    for (int k = 0; k < KNN; ++k) {
        s_md[tid * KNN + k] = bd[k];
        s_mi[tid * KNN + k] = bi[k];
    }
    __syncthreads();

    // Threads 0..63 merge their query's two sorted lists (exact ordering:
    // on equal d2, group 0 wins since all its indices are lower).
    if (tid < QPB) {
        const int a = qloc * KNN;                 // group 0 list
        const int b = (QPB + qloc) * KNN;         // group 1 list
        int ia = 0, ib = 0;
        int fi[KNN];
#pragma unroll
        for (int k = 0; k < KNN; ++k) {
            const float da = s_md[a + ia];
            const float db = s_md[b + ib];
            if (da <= db) { fi[k] = s_mi[a + ia]; ++ia; }
            else          { fi[k] = s_mi[b + ib]; ++ib; }
        }

        // ---- gather features and apply collapsed linear head ----
        float acc[6];
#pragma unroll
        for (int c = 0; c < 6; ++c) acc[c] = s_bc[c];

        // rows 0..32: neighbor velocities (incl. self, rank order)
#pragma unroll
        for (int r = 0; r < KNN; ++r) {
            const int j = fi[r];
            const float vx = bvel[j * 3 + 0];
            const float vy = bvel[j * 3 + 1];
            const float vz = bvel[j * 3 + 2];
            const int row = 3 * r;
#pragma unroll
            for (int c = 0; c < 6; ++c) {
                acc[c] = fmaf(vx, s_Wc[(row + 0) * 6 + c], acc[c]);
                acc[c] = fmaf(vy, s_Wc[(row + 1) * 6 + c], acc[c]);
                acc[c] = fmaf(vz, s_Wc[(row + 2) * 6 + c], acc[c]);
            }
        }
        // rows 33..62: neighbor position offsets (excl. self)
#pragma unroll
        for (int r = 1; r < KNN; ++r) {
            const int j = fi[r];
            const float ox = bpos[j * 3 + 0] - qx;
            const float oy = bpos[j * 3 + 1] - qy;
            const float oz = bpos[j * 3 + 2] - qz;
            const int row = 33 + 3 * (r - 1);
#pragma unroll
            for (int c = 0; c < 6; ++c) {
                acc[c] = fmaf(ox, s_Wc[(row + 0) * 6 + c], acc[c]);
                acc[c] = fmaf(oy, s_Wc[(row + 1) * 6 + c], acc[c]);
                acc[c] = fmaf(oz, s_Wc[(row + 2) * 6 + c], acc[c]);
            }
        }
        // rows 63..65: init_config
        {
            const float i0 = initc[bb * 3 + 0];
            const float i1 = initc[bb * 3 + 1];
            const float i2 = initc[bb * 3 + 2];
#pragma unroll
            for (int c = 0; c < 6; ++c) {
                acc[c] = fmaf(i0, s_Wc[63 * 6 + c], acc[c]);
                acc[c] = fmaf(i1, s_Wc[64 * 6 + c], acc[c]);
                acc[c] = fmaf(i2, s_Wc[65 * 6 + c], acc[c]);
            }
        }

        float* o = out + (size_t)q * 6;
        o[0] = acc[0] + qx;
        o[1] = acc[1] + qy;
        o[2] = acc[2] + qz;
        o[3] = acc[3];
        o[4] = acc[4];
        o[5] = acc[5];
    }
}

// ---------------------------------------------------------------------------
extern "C" void kernel_launch(void* const* d_in, const int* in_sizes, int n_in,
                              void* d_out, int out_size)
{
    const float* position = (const float*)d_in[0];
    const float* velocity = (const float*)d_in[1];
    const float* initcfg  = (const float*)d_in[2];
    const float* W1 = (const float*)d_in[3];
    const float* b1 = (const float*)d_in[4];
    const float* W2 = (const float*)d_in[5];
    const float* b2 = (const float*)d_in[6];
    const float* W3 = (const float*)d_in[7];
    const float* b3 = (const float*)d_in[8];
    float* out = (float*)d_out;

    combine_weights_kernel<<<1, 256>>>(W1, b1, W2, b2, W3, b3);

    const int total = BATCH * NPTS;           // 16384 queries
    knn_mlp_kernel<<<total / QPB, TPB>>>(position, velocity, initcfg, out);
}